// round 1
// baseline (speedup 1.0000x reference)
#include <cuda_runtime.h>
#include <math.h>

#define NSEQ 2048
#define CDIM 1024
#define HH 16
#define DD 64
#define FDIM 3072

// ---------------- scratch (static device allocations; no cudaMalloc) --------
__device__ float g_qkv[NSEQ * FDIM];                    // 25 MB
__device__ float g_qn[HH * NSEQ * DD];                  // 8 MB
__device__ float g_kn[HH * NSEQ * DD];                  // 8 MB
__device__ float g_v [HH * NSEQ * DD];                  // 8 MB
__device__ float g_S [67108864];                        // 16*2048*2048 fp32 = 256 MB
__device__ float g_m [HH * NSEQ];
__device__ float g_l [HH * NSEQ];
__device__ float g_oa[NSEQ * CDIM];                     // attn@V, [n][(h d)] layout
__device__ float g_sumv[HH * DD];

// ---------------- generic C = A * B^T tiled GEMM ---------------------------
// A: M x K row-major, B: N x K row-major, C: M x N row-major.
// BM=BN=64, BK=16, 256 threads, 4x4 micro-tile. All dims multiples of 64/16.
__global__ __launch_bounds__(256) void gemm_abt(
    const float* __restrict__ A, const float* __restrict__ B,
    float* __restrict__ C, int M, int Nn, int K)
{
    __shared__ float As[16][64];
    __shared__ float Bs[16][64];
    int bm = blockIdx.y, bn = blockIdx.x;
    int tid = threadIdx.x;
    int tx = tid & 15, ty = tid >> 4;

    float acc[4][4] = {};
    for (int k0 = 0; k0 < K; k0 += 16) {
        #pragma unroll
        for (int l = 0; l < 4; l++) {
            int idx = tid + l * 256;
            int m = idx >> 4, kk = idx & 15;
            As[kk][m] = A[(size_t)(bm * 64 + m) * K + k0 + kk];
        }
        #pragma unroll
        for (int l = 0; l < 4; l++) {
            int idx = tid + l * 256;
            int n = idx >> 4, kk = idx & 15;
            Bs[kk][n] = B[(size_t)(bn * 64 + n) * K + k0 + kk];
        }
        __syncthreads();
        #pragma unroll
        for (int kk = 0; kk < 16; kk++) {
            float a[4], b[4];
            #pragma unroll
            for (int i = 0; i < 4; i++) a[i] = As[kk][ty * 4 + i];
            #pragma unroll
            for (int j = 0; j < 4; j++) b[j] = Bs[kk][tx * 4 + j];
            #pragma unroll
            for (int i = 0; i < 4; i++)
                #pragma unroll
                for (int j = 0; j < 4; j++) acc[i][j] = fmaf(a[i], b[j], acc[i][j]);
        }
        __syncthreads();
    }
    #pragma unroll
    for (int i = 0; i < 4; i++)
        #pragma unroll
        for (int j = 0; j < 4; j++)
            C[(size_t)(bm * 64 + ty * 4 + i) * Nn + bn * 64 + tx * 4 + j] = acc[i][j];
}

// ---------------- split qkv, l2-normalize q/k, emit kv outputs -------------
// qkv layout per reference: f = (h*D + d)*3 + {q,k,v}
__global__ void split_norm(float* __restrict__ kout, float* __restrict__ vout)
{
    int n = blockIdx.x, h = blockIdx.y, d = threadIdx.x;   // 64 threads
    int base = n * FDIM + (h * DD + d) * 3;
    float q = g_qkv[base + 0];
    float k = g_qkv[base + 1];
    float v = g_qkv[base + 2];

    float sq = q * q, sk = k * k;
    #pragma unroll
    for (int off = 16; off > 0; off >>= 1) {
        sq += __shfl_xor_sync(0xffffffffu, sq, off);
        sk += __shfl_xor_sync(0xffffffffu, sk, off);
    }
    __shared__ float red[4];
    int w = d >> 5, lane = d & 31;
    if (lane == 0) { red[w] = sq; red[2 + w] = sk; }
    __syncthreads();
    float nq = sqrtf(red[0] + red[1]);
    float nk = sqrtf(red[2] + red[3]);

    int o = (h * NSEQ + n) * DD + d;
    g_qn[o] = q / fmaxf(nq, 1e-12f);
    g_kn[o] = k / fmaxf(nk, 1e-12f);
    kout[o] = k;
    vout[o] = v;
    g_v[o]  = v;
}

// ---------------- sum of V over sequence (for b_post term) -----------------
__global__ void sumv_k()
{
    int g = blockIdx.x, d = threadIdx.x;
    float s = 0.f;
    for (int j = 0; j < NSEQ; j++) s += g_v[(g * NSEQ + j) * DD + d];
    g_sumv[g * DD + d] = s;
}

// ---------------- fused scores: cosine dots (all heads) + temp + pre-mix ---
// CTA = 32x32 causal (i,j) tile; raw scores for 16 heads kept in registers,
// talking-heads pre-mix + b_pre + pos_bias applied, S written pre-softmax.
__global__ __launch_bounds__(256) void scores_k(
    const float* __restrict__ Wpre, const float* __restrict__ bpre,
    const float* __restrict__ pb, const float* __restrict__ temp_p)
{
    int it = blockIdx.y, jt = blockIdx.x;
    if (jt > it) return;                   // fully masked tile

    __shared__ float qs[32][65];
    __shared__ float ks[32][65];
    __shared__ float wpre_s[256];
    __shared__ float bpre_s[16];

    int tid = threadIdx.x;
    wpre_s[tid < 256 ? tid : 0] = Wpre[tid < 256 ? tid : 0];
    if (tid < 16) bpre_s[tid] = bpre[tid];

    float temp = __ldg(temp_p);
    int tx = tid & 15, ty = tid >> 4;
    int i0 = it * 32, j0 = jt * 32;

    float raw[16][4];
    #pragma unroll
    for (int h = 0; h < 16; h++) {
        __syncthreads();
        #pragma unroll
        for (int l = 0; l < 8; l++) {
            int idx = tid + l * 256;
            int r = idx >> 6, dd = idx & 63;
            qs[r][dd] = g_qn[(h * NSEQ + i0 + r) * DD + dd];
            ks[r][dd] = g_kn[(h * NSEQ + j0 + r) * DD + dd];
        }
        __syncthreads();
        float a00 = 0.f, a01 = 0.f, a10 = 0.f, a11 = 0.f;
        #pragma unroll 8
        for (int kk = 0; kk < 64; kk++) {
            float q0 = qs[ty * 2 + 0][kk];
            float q1 = qs[ty * 2 + 1][kk];
            float k0 = ks[tx * 2 + 0][kk];
            float k1 = ks[tx * 2 + 1][kk];
            a00 = fmaf(q0, k0, a00); a01 = fmaf(q0, k1, a01);
            a10 = fmaf(q1, k0, a10); a11 = fmaf(q1, k1, a11);
        }
        raw[h][0] = a00 * temp; raw[h][1] = a01 * temp;
        raw[h][2] = a10 * temp; raw[h][3] = a11 * temp;
    }

    int ibase = i0 + ty * 2;
    int jbase = j0 + tx * 2;
    #pragma unroll
    for (int g = 0; g < 16; g++) {
        #pragma unroll
        for (int e = 0; e < 4; e++) {
            float acc = bpre_s[g];
            #pragma unroll
            for (int h = 0; h < 16; h++)
                acc = fmaf(wpre_s[g * 16 + h], raw[h][e], acc);
            int ii = ibase + (e >> 1);
            int jj = jbase + (e & 1);
            size_t idx = ((size_t)(g * NSEQ + ii)) * NSEQ + jj;
            g_S[idx] = acc + pb[idx];
        }
    }
}

// ---------------- per-row online max / sum-exp ------------------------------
__global__ __launch_bounds__(256) void rowstat_k()
{
    int i = blockIdx.x, g = blockIdx.y;
    const float* row = g_S + ((size_t)(g * NSEQ + i)) * NSEQ;
    int tid = threadIdx.x;

    float m = -INFINITY, l = 0.f;
    for (int j = tid; j <= i; j += 256) {
        float s = row[j];
        float nm = fmaxf(m, s);
        l = l * __expf(m - nm) + __expf(s - nm);
        m = nm;
    }
    __shared__ float sm[256], sl[256];
    sm[tid] = m; sl[tid] = l;
    __syncthreads();
    for (int s = 128; s > 0; s >>= 1) {
        if (tid < s) {
            float m1 = sm[tid], l1 = sl[tid];
            float m2 = sm[tid + s], l2 = sl[tid + s];
            float M = fmaxf(m1, m2);
            float L = (M == -INFINITY) ? 0.f
                      : l1 * __expf(m1 - M) + l2 * __expf(m2 - M);
            sm[tid] = M; sl[tid] = L;
        }
        __syncthreads();
    }
    if (tid == 0) { g_m[g * NSEQ + i] = sm[0]; g_l[g * NSEQ + i] = sl[0]; }
}

// ---------------- softmax normalize + talking-heads post-mix (in place) ----
__global__ __launch_bounds__(256) void postmix_k(const float* __restrict__ Wpost)
{
    __shared__ float w[256];
    int tid = threadIdx.x;
    w[tid] = Wpost[tid];
    int i = blockIdx.y;
    int j = blockIdx.x * 256 + tid;
    __syncthreads();
    if (j > i) return;

    float a[16];
    #pragma unroll
    for (int h = 0; h < 16; h++) {
        size_t idx = ((size_t)(h * NSEQ + i)) * NSEQ + j;
        float s = g_S[idx];
        a[h] = __expf(s - g_m[h * NSEQ + i]) / g_l[h * NSEQ + i];
    }
    #pragma unroll
    for (int g = 0; g < 16; g++) {
        float val = 0.f;
        #pragma unroll
        for (int h = 0; h < 16; h++) val = fmaf(w[g * 16 + h], a[h], val);
        g_S[((size_t)(g * NSEQ + i)) * NSEQ + j] = val;
    }
}

// ---------------- causal attn @ V  →  oa[n][(g d)] --------------------------
__global__ __launch_bounds__(256) void av_k(const float* __restrict__ bpost)
{
    int itile = blockIdx.x, g = blockIdx.y;
    __shared__ float Ssm[64][65];
    __shared__ float Vsm[64][64];
    int tid = threadIdx.x;
    int tx = tid & 15, ty = tid >> 4;
    int i0 = itile * 64;

    float acc[4][4] = {};
    for (int j0 = 0; j0 <= i0; j0 += 64) {
        bool diag = (j0 == i0);
        #pragma unroll
        for (int l = 0; l < 16; l++) {
            int idx = tid + l * 256;
            int r = idx >> 6, c = idx & 63;
            float s = 0.f;
            if (!diag || (j0 + c <= i0 + r))
                s = g_S[((size_t)(g * NSEQ + i0 + r)) * NSEQ + j0 + c];
            Ssm[r][c] = s;
            Vsm[r][c] = g_v[(g * NSEQ + j0 + r) * DD + c];
        }
        __syncthreads();
        #pragma unroll 8
        for (int kk = 0; kk < 64; kk++) {
            float a[4], b[4];
            #pragma unroll
            for (int i = 0; i < 4; i++) a[i] = Ssm[ty * 4 + i][kk];
            #pragma unroll
            for (int j = 0; j < 4; j++) b[j] = Vsm[kk][tx * 4 + j];
            #pragma unroll
            for (int i = 0; i < 4; i++)
                #pragma unroll
                for (int j = 0; j < 4; j++) acc[i][j] = fmaf(a[i], b[j], acc[i][j]);
        }
        __syncthreads();
    }
    float bp = bpost[g];
    #pragma unroll
    for (int i = 0; i < 4; i++)
        #pragma unroll
        for (int j = 0; j < 4; j++) {
            int d = tx * 4 + j;
            g_oa[(size_t)(i0 + ty * 4 + i) * CDIM + g * DD + d] =
                acc[i][j] + bp * g_sumv[g * DD + d];
        }
}

// ---------------- launch -----------------------------------------------------
extern "C" void kernel_launch(void* const* d_in, const int* in_sizes, int n_in,
                              void* d_out, int out_size)
{
    const float* x     = (const float*)d_in[0];
    const float* pb    = (const float*)d_in[1];
    // d_in[2] = mask: causal, applied analytically
    const float* Wqkv  = (const float*)d_in[3];
    const float* Wout  = (const float*)d_in[4];
    const float* temp  = (const float*)d_in[5];
    const float* Wpre  = (const float*)d_in[6];
    const float* bpre  = (const float*)d_in[7];
    const float* Wpost = (const float*)d_in[8];
    const float* bpost = (const float*)d_in[9];

    float* out  = (float*)d_out;                 // [2048, 1024]
    float* kout = out + NSEQ * CDIM;             // kv[0] = k  [16,2048,64]
    float* vout = kout + HH * NSEQ * DD;         // kv[1] = v

    void *p_qkv, *p_oa;
    cudaGetSymbolAddress(&p_qkv, g_qkv);
    cudaGetSymbolAddress(&p_oa,  g_oa);

    // 1. qkv = x @ W_qkv^T
    gemm_abt<<<dim3(FDIM / 64, NSEQ / 64), 256>>>(x, Wqkv, (float*)p_qkv,
                                                  NSEQ, FDIM, CDIM);
    // 2. split + l2norm + kv outputs
    split_norm<<<dim3(NSEQ, HH), 64>>>(kout, vout);
    // 3. sum_j v  (b_post term)
    sumv_k<<<HH, DD>>>();
    // 4. scores: dots*temp -> pre-mix -> +pos_bias (causal tiles only)
    scores_k<<<dim3(64, 64), 256>>>(Wpre, bpre, pb, temp);
    // 5. row max / sum-exp
    rowstat_k<<<dim3(NSEQ, HH), 256>>>();
    // 6. softmax + post-mix (in place)
    postmix_k<<<dim3(NSEQ / 256, NSEQ), 256>>>(Wpost);
    // 7. attn @ V  (+ b_post * sum v)
    av_k<<<dim3(NSEQ / 64, HH), 256>>>(bpost);
    // 8. out = oa @ W_out^T
    gemm_abt<<<dim3(CDIM / 64, NSEQ / 64), 256>>>((const float*)p_oa, Wout, out,
                                                  NSEQ, CDIM, CDIM);
}